// round 3
// baseline (speedup 1.0000x reference)
#include <cuda_runtime.h>
#include <cstdint>

#define NE    8192
#define DIM   128
#define PMAX  5
#define NNODE 512
#define TOTAL (NNODE * NNODE)

#define CTAS        128
#define THREADS     1024
#define CLUSTER     4
#define EDGES_CTA   (NE / CTAS)          // 64
#define PAIRS_CTA   (TOTAL / CTAS)       // 2048
#define TBL_BYTES   (PMAX * NE * 4)      // 163840
#define SLICE_BYTES (TBL_BYTES / CLUSTER)// 40960
#define STAGE_INT4  (PAIRS_CTA * PMAX / 4) // 2560
#define STAGE_BYTES (STAGE_INT4 * 16)    // 40960
#define SMEM_TOTAL  (TBL_BYTES + STAGE_BYTES)

__device__ float g_dots[PMAX * NE];
__device__ int   g_ctr = 0;   // monotone across graph replays (generation barrier)

__device__ __forceinline__ uint32_t smem_u32(const void* p) {
    return (uint32_t)__cvta_generic_to_shared(p);
}

__global__ __launch_bounds__(THREADS, 1) __cluster_dims__(CLUSTER, 1, 1)
void fused_kernel(const float* __restrict__ emb,
                  const float* __restrict__ ev,
                  const int*   __restrict__ paths,
                  float*       __restrict__ out) {
    extern __shared__ __align__(16) char smem[];
    float* s_dots  = (float*)smem;                 // 163840 B
    int*   s_paths = (int*)(smem + TBL_BYTES);     // 40960 B
    __shared__ __align__(8) unsigned long long mbar;

    const int tid  = threadIdx.x;
    const int lane = tid & 31;
    const int w    = tid >> 5;

    // ---- issue path-index loads immediately (coalesced int4, DRAM in flight)
    const int4* psrc = (const int4*)paths + blockIdx.x * STAGE_INT4;
    int4 pv0 = __ldg(psrc + tid);
    int4 pv1 = __ldg(psrc + tid + 1024);
    int4 pv2;
    if (tid < STAGE_INT4 - 2048) pv2 = __ldg(psrc + tid + 2048);

    // ---- mbarrier init + cluster visibility
    const uint32_t mb = smem_u32(&mbar);
    if (tid == 0)
        asm volatile("mbarrier.init.shared.b64 [%0], 1;" :: "r"(mb));
    __syncthreads();
    asm volatile("barrier.cluster.arrive.aligned;" ::: "memory");
    asm volatile("barrier.cluster.wait.aligned;"   ::: "memory");

    // ---- dot phase: this CTA computes edges [b*64, b*64+64); warp -> 2 edges
    {
        float4 evr[PMAX];
#pragma unroll
        for (int p = 0; p < PMAX; ++p)
            evr[p] = __ldg(((const float4*)ev) + p * (DIM / 4) + lane);

        const int e0 = blockIdx.x * EDGES_CTA + w * 2;
        float4 a0 = __ldg(((const float4*)emb) + (e0    ) * (DIM / 4) + lane);
        float4 a1 = __ldg(((const float4*)emb) + (e0 + 1) * (DIM / 4) + lane);

        float pa[PMAX], pb[PMAX];
#pragma unroll
        for (int p = 0; p < PMAX; ++p) {
            pa[p] = a0.x * evr[p].x + a0.y * evr[p].y + a0.z * evr[p].z + a0.w * evr[p].w;
            pb[p] = a1.x * evr[p].x + a1.y * evr[p].y + a1.z * evr[p].z + a1.w * evr[p].w;
        }
#pragma unroll
        for (int off = 16; off > 0; off >>= 1) {
#pragma unroll
            for (int p = 0; p < PMAX; ++p) {
                pa[p] += __shfl_xor_sync(0xffffffffu, pa[p], off);
                pb[p] += __shfl_xor_sync(0xffffffffu, pb[p], off);
            }
        }
        if (lane == 0) {
#pragma unroll
            for (int p = 0; p < PMAX; ++p) {
                g_dots[p * NE + e0]     = pa[p];
                g_dots[p * NE + e0 + 1] = pb[p];
            }
        }
    }

    // ---- stage path indices into smem
    {
        int4* st = (int4*)s_paths;
        st[tid]        = pv0;
        st[tid + 1024] = pv1;
        if (tid < STAGE_INT4 - 2048) st[tid + 2048] = pv2;
    }
    __syncthreads();

    // ---- grid-wide generation barrier + multicast table fill (tid 0 only)
    if (tid == 0) {
        __threadfence();                       // g_dots STGs visible GPU-wide
        int old = atomicAdd(&g_ctr, 1);
        int target = (old / CTAS + 1) * CTAS;
        volatile int* vc = &g_ctr;
        while (*vc < target) { }
        __threadfence();                       // acquire
        asm volatile("fence.proxy.async;" ::: "memory");

        asm volatile("mbarrier.arrive.expect_tx.shared.b64 _, [%0], %1;"
                     :: "r"(mb), "r"((uint32_t)TBL_BYTES) : "memory");

        uint32_t rank;
        asm("mov.u32 %0, %%cluster_ctarank;" : "=r"(rank));
        uint32_t    dst = smem_u32(s_dots) + rank * SLICE_BYTES;
        const char* src = (const char*)g_dots + rank * SLICE_BYTES;
        asm volatile(
            "cp.async.bulk.shared::cluster.global.mbarrier::complete_tx::bytes"
            ".multicast::cluster [%0], [%1], %2, [%3], %4;"
            :: "r"(dst), "l"(src), "r"((uint32_t)SLICE_BYTES), "r"(mb),
               "h"((unsigned short)((1u << CLUSTER) - 1u))
            : "memory");
    }

    // ---- wait for full table (4 slices x 40KB multicast into this CTA)
    {
        uint32_t done;
        asm volatile(
            "{\n\t.reg .pred p;\n\t"
            "mbarrier.try_wait.parity.acquire.cta.shared::cta.b64 p, [%1], 0;\n\t"
            "selp.b32 %0, 1, 0, p;\n\t}"
            : "=r"(done) : "r"(mb) : "memory");
        while (!done) {
            asm volatile(
                "{\n\t.reg .pred p;\n\t"
                "mbarrier.try_wait.parity.acquire.cta.shared::cta.b64 p, [%1], 0, 0x989680;\n\t"
                "selp.b32 %0, 1, 0, p;\n\t}"
                : "=r"(done) : "r"(mb) : "memory");
        }
    }

    // ---- gather: thread t handles pairs (2t, 2t+1) of this CTA
    {
        const int* sp = s_paths + 10 * tid;
        float acc0 = 0.0f, acc1 = 0.0f;
        int   c0 = 0, c1 = 0;
#pragma unroll
        for (int p = 0; p < PMAX; ++p) {
            int e = sp[p];
            if (e >= 0) { acc0 += s_dots[p * NE + e]; ++c0; }
        }
#pragma unroll
        for (int p = 0; p < PMAX; ++p) {
            int e = sp[PMAX + p];
            if (e >= 0) { acc1 += s_dots[p * NE + e]; ++c1; }
        }
        float2 r;
        r.x = c0 ? acc0 / (float)c0 : 0.0f;
        r.y = c1 ? acc1 / (float)c1 : 0.0f;
        ((float2*)out)[blockIdx.x * THREADS + tid] = r;
    }
}

extern "C" void kernel_launch(void* const* d_in, const int* in_sizes, int n_in,
                              void* d_out, int out_size) {
    const float* emb   = nullptr;
    const int*   paths = nullptr;
    const float* ev    = nullptr;
    for (int i = 0; i < n_in; ++i) {
        if (in_sizes[i] == NE * DIM)                  emb   = (const float*)d_in[i];
        else if (in_sizes[i] == NNODE * NNODE * PMAX) paths = (const int*)d_in[i];
        else if (in_sizes[i] == PMAX * DIM)           ev    = (const float*)d_in[i];
    }
    float* out = (float*)d_out;

    cudaFuncSetAttribute(fused_kernel,
                         cudaFuncAttributeMaxDynamicSharedMemorySize,
                         SMEM_TOTAL);
    fused_kernel<<<CTAS, THREADS, SMEM_TOTAL>>>(emb, ev, paths, out);
}